// round 13
// baseline (speedup 1.0000x reference)
#include <cuda_runtime.h>
#include <cuda_fp16.h>
#include <cstdint>
#include <cstddef>

// Problem dims
#define M_DIM 8192
#define K_DIM 4096
#define N_DIM 11008

// GEMM tiling (single-plane fp16, legacy HMMA rt=4; pair-staged + frag-pipelined)
#define BM 256
#define BN 128
#define BKE 64                  // K elements (fp16) per stage = 128 bytes per row
#define NPAIR (K_DIM / (2 * BKE))   // 32 pair-iterations
#define THREADS 256             // 8 warps, 4(m) x 2(n) grid, 64x64 warp tile
#define ROWBYTES 128            // XOR-swizzled rows, no padding
#define TILE_A (BM * ROWBYTES)              // 32768
#define TILE_W (BN * ROWBYTES)              // 16384
#define STAGE_BYTES (TILE_A + TILE_W)       // 49152: A | W
#define SMEM_BYTES (4 * STAGE_BYTES)        // 196608 (2 pair-buffers)

// Scratch (device globals — no runtime allocation allowed)
__device__ __half g_xh[(size_t)M_DIM * K_DIM];   // x as fp16 (11-bit mantissa)
__device__ __half g_w [(size_t)N_DIM * K_DIM];   // Wq as fp16 (exact, |w|<=127)

// ---------------- PTX helpers (portable ISA only: sm_80+) ----------------
__device__ __forceinline__ uint32_t smem_u32(const void* p) {
    uint32_t a;
    asm("{ .reg .u64 t; cvta.to.shared.u64 t, %1; cvt.u32.u64 %0, t; }"
        : "=r"(a) : "l"(p));
    return a;
}
__device__ __forceinline__ void cp16(uint32_t s, const void* g) {
    asm volatile("cp.async.cg.shared.global [%0], [%1], 16;" :: "r"(s), "l"(g) : "memory");
}
#define CP_COMMIT() asm volatile("cp.async.commit_group;" ::: "memory")
#define CP_WAIT(n)  asm volatile("cp.async.wait_group %0;" :: "n"(n) : "memory")

__device__ __forceinline__ void ldsm4(uint32_t* d, uint32_t addr) {
    asm volatile("ldmatrix.sync.aligned.m8n8.x4.shared.b16 {%0,%1,%2,%3}, [%4];"
                 : "=r"(d[0]), "=r"(d[1]), "=r"(d[2]), "=r"(d[3]) : "r"(addr));
}
// C(f32) += A(16x16 f16) * B(16x8 f16)^T
__device__ __forceinline__ void mma_f16(float* c, const uint32_t* a, uint32_t b0, uint32_t b1) {
    asm volatile(
        "mma.sync.aligned.m16n8k16.row.col.f32.f16.f16.f32 "
        "{%0,%1,%2,%3},{%4,%5,%6,%7},{%8,%9},{%0,%1,%2,%3};"
        : "+f"(c[0]), "+f"(c[1]), "+f"(c[2]), "+f"(c[3])
        : "r"(a[0]), "r"(a[1]), "r"(a[2]), "r"(a[3]), "r"(b0), "r"(b1));
}

// ---------------- prepass 1: x -> fp16 ----------------
__global__ void cvt_x_kernel(const float4* __restrict__ x, int n4) {
    int i = blockIdx.x * blockDim.x + threadIdx.x;
    if (i >= n4) return;
    float4 v = x[i];
    __half2 a = __floats2half2_rn(v.x, v.y);
    __half2 b = __floats2half2_rn(v.z, v.w);
    uint2 o = make_uint2(*reinterpret_cast<uint32_t*>(&a), *reinterpret_cast<uint32_t*>(&b));
    reinterpret_cast<uint2*>(g_xh)[i] = o;
}

// ---------------- prepass 2: Wq int32 -> fp16 (exact for |w|<=127) ----------------
__global__ void cvt_w_kernel(const int4* __restrict__ wq, int n4) {
    int i = blockIdx.x * blockDim.x + threadIdx.x;
    if (i >= n4) return;
    int4 q = wq[i];
    __half2 a = __floats2half2_rn((float)q.x, (float)q.y);
    __half2 b = __floats2half2_rn((float)q.z, (float)q.w);
    uint2 o = make_uint2(*reinterpret_cast<uint32_t*>(&a), *reinterpret_cast<uint32_t*>(&b));
    reinterpret_cast<uint2*>(g_w)[i] = o;
}

// ---------------- GEMM ----------------
// XOR swizzle: row r (128B), 16B chunk c stored at chunk (c ^ (r&7))
__device__ __forceinline__ void load_stage(uint32_t sbase,
                                           const __half* __restrict__ Ax,
                                           const __half* __restrict__ Bw,
                                           int kc, int tid) {
    const int kb = kc * BKE;
    // A: 256 rows x 8 chunks = 2048 chunks; 8 per thread
#pragma unroll
    for (int i = 0; i < 8; ++i) {
        const int q = i * THREADS + tid;
        const int r = q >> 3, c = q & 7;
        const uint32_t so = (uint32_t)r * ROWBYTES + ((c ^ (r & 7)) << 4);
        const size_t ge = (size_t)r * K_DIM + kb + c * 8;
        cp16(sbase + so, Ax + ge);
    }
    // W: 128 rows x 8 chunks = 1024 chunks; 4 per thread
#pragma unroll
    for (int i = 0; i < 4; ++i) {
        const int q = i * THREADS + tid;
        const int r = q >> 3, c = q & 7;
        const uint32_t so = (uint32_t)r * ROWBYTES + ((c ^ (r & 7)) << 4);
        const size_t ge = (size_t)r * K_DIM + kb + c * 8;
        cp16(sbase + TILE_A + so, Bw + ge);
    }
}

// Per-thread fragment addressing layout (hoisted out of the mainloop)
struct FragLayout {
    uint32_t aBase[4];
    uint32_t bBase[4];
    int ax[4];
    int bx;
    int ac0, bc0;
};

__device__ __forceinline__ void make_layout(FragLayout& f, int l, int wm, int wn) {
    const int r = l & 7, mi = l >> 3;
    const int arow = ((mi & 1) << 3) + r;
    f.ac0 = (mi >> 1);
#pragma unroll
    for (int i = 0; i < 4; ++i) {
        const int rowi = wm + arow + 16 * i;
        f.aBase[i] = (uint32_t)rowi * ROWBYTES;
        f.ax[i] = rowi & 7;
    }
    const int brow = wn + ((mi >> 1) << 3) + r;
    f.bc0 = (mi & 1);
#pragma unroll
    for (int nb = 0; nb < 4; ++nb)
        f.bBase[nb] = (uint32_t)(brow + 16 * nb) * ROWBYTES;
    f.bx = brow & 7;   // invariant under +16
}

// Load one k-step's fragments (4 A ldsm4 + 4 B ldsm4) from stage `st`
__device__ __forceinline__ void ld_frags(uint32_t st, int ks, const FragLayout& f,
                                         uint32_t a[4][4], uint32_t bt[4][4]) {
    const int ca = f.ac0 + 2 * ks;
    const int cb = f.bc0 + 2 * ks;
    const uint32_t bB = st + TILE_A;
#pragma unroll
    for (int nb = 0; nb < 4; ++nb)
        ldsm4(bt[nb], bB + f.bBase[nb] + (uint32_t)((cb ^ f.bx) << 4));
#pragma unroll
    for (int i = 0; i < 4; ++i)
        ldsm4(a[i], st + f.aBase[i] + (uint32_t)((ca ^ f.ax[i]) << 4));
}

__device__ __forceinline__ void do_mmas(const uint32_t a[4][4], const uint32_t bt[4][4],
                                        float c[4][8][4]) {
#pragma unroll
    for (int i = 0; i < 4; ++i) {
#pragma unroll
        for (int j = 0; j < 8; ++j) {
            mma_f16(c[i][j], a[i], bt[j >> 1][(j & 1) * 2], bt[j >> 1][(j & 1) * 2 + 1]);
        }
    }
}

__global__ void __launch_bounds__(THREADS, 1)
gemm_kernel(const float* __restrict__ scale, const float* __restrict__ bias,
            float* __restrict__ out) {
    extern __shared__ char smem[];
    const uint32_t sb = smem_u32(smem);
    const int tid = threadIdx.x;
    const int wid = tid >> 5;        // 0..7
    const int l = tid & 31;

    const int nt = blockIdx.x;   // fastest -> W (90MB) stays L2-resident across mt sweep
    const int mt = blockIdx.y;
    const size_t mBase = (size_t)mt * BM;
    const size_t nBase = (size_t)nt * BN;

    const __half* Ax = g_xh + mBase * K_DIM;
    const __half* Bw = g_w + nBase * K_DIM;

    const int wm = (wid & 3) * 64;   // 4(m) x 2(n) warp grid, 64x64 warp tile
    const int wn = (wid >> 2) * 64;

    FragLayout fl;
    make_layout(fl, l, wm, wn);

    float c[4][8][4];                // 128 f32 accumulators
#pragma unroll
    for (int i = 0; i < 4; ++i)
#pragma unroll
        for (int j = 0; j < 8; ++j)
#pragma unroll
            for (int k = 0; k < 4; ++k) c[i][j][k] = 0.0f;

    // prologue: pair 0 (stages 0,1) into pair-buffer 0
    load_stage(sb + 0 * STAGE_BYTES, Ax, Bw, 0, tid);
    load_stage(sb + 1 * STAGE_BYTES, Ax, Bw, 1, tid);
    CP_COMMIT();

    // Pair-staged mainloop: one wait + one sync per TWO K-stages (32 total).
    // Within a pair: 8 k-steps, fragments double-buffered (prefetch t+1 during mma t)
    uint32_t afr[2][4][4], bfr[2][4][4];
    for (int p = 0; p < NPAIR; ++p) {
        CP_WAIT(0);                // pair p resident
        __syncthreads();           // all warps done with pair p-1's buffers
        const uint32_t cur = sb + (uint32_t)(p & 1) * (2 * STAGE_BYTES);
        const uint32_t nxt = sb + (uint32_t)((p + 1) & 1) * (2 * STAGE_BYTES);
        if (p + 1 < NPAIR) {
            load_stage(nxt,               Ax, Bw, 2 * p + 2, tid);
            load_stage(nxt + STAGE_BYTES, Ax, Bw, 2 * p + 3, tid);
            CP_COMMIT();
        }
        // 8-k-step software pipeline over stages {cur, cur+STAGE_BYTES}
        ld_frags(cur, 0, fl, afr[0], bfr[0]);
#pragma unroll
        for (int t = 0; t < 8; ++t) {
            if (t + 1 < 8) {
                const uint32_t stn = (t + 1 < 4) ? cur : (cur + STAGE_BYTES);
                ld_frags(stn, (t + 1) & 3, fl, afr[(t + 1) & 1], bfr[(t + 1) & 1]);
            }
            do_mmas(afr[t & 1], bfr[t & 1], c);
        }
    }

    // ---------------- epilogue: scale + bias + exact GELU ----------------
    const int gid = l >> 2, tig = l & 3;

    float wv[16], bv[16];
#pragma unroll
    for (int j = 0; j < 8; ++j) {
        const size_t n0 = nBase + wn + 8 * j + 2 * tig;
        wv[2 * j] = scale[n0]; wv[2 * j + 1] = scale[n0 + 1];
        bv[2 * j] = bias[n0];  bv[2 * j + 1] = bias[n0 + 1];
    }

#pragma unroll
    for (int i = 0; i < 4; ++i) {
#pragma unroll
        for (int j = 0; j < 8; ++j) {
            const size_t n0 = nBase + wn + 8 * j + 2 * tig;
#pragma unroll
            for (int h = 0; h < 2; ++h) {
                const size_t m = mBase + wm + 16 * i + gid + 8 * h;
                float y0 = fmaf(c[i][j][2 * h],     wv[2 * j],     bv[2 * j]);
                float y1 = fmaf(c[i][j][2 * h + 1], wv[2 * j + 1], bv[2 * j + 1]);
                float g0 = 0.5f * y0 * (1.0f + erff(y0 * 0.70710678118654752f));
                float g1 = 0.5f * y1 * (1.0f + erff(y1 * 0.70710678118654752f));
                float2 vv; vv.x = g0; vv.y = g1;
                __stcg(reinterpret_cast<float2*>(out + m * N_DIM + n0), vv);
            }
        }
    }
}

// ---------------- launch ----------------
extern "C" void kernel_launch(void* const* d_in, const int* in_sizes, int n_in,
                              void* d_out, int out_size) {
    const float* x     = (const float*)d_in[0];
    const int*   Wq    = (const int*)d_in[1];
    const float* scale = (const float*)d_in[2];
    const float* bias  = (const float*)d_in[3];
    float* out = (float*)d_out;
    (void)in_sizes; (void)n_in; (void)out_size;

    // x -> fp16
    {
        const int n4 = (M_DIM * K_DIM) / 4;   // 8388608
        cvt_x_kernel<<<(n4 + 255) / 256, 256>>>((const float4*)x, n4);
    }
    // Wq int32 -> fp16 (exact)
    {
        const int n4 = (N_DIM * K_DIM) / 4;   // 11272192
        cvt_w_kernel<<<(n4 + 255) / 256, 256>>>((const int4*)Wq, n4);
    }
    // GEMM + fused epilogue
    cudaFuncSetAttribute(gemm_kernel, cudaFuncAttributeMaxDynamicSharedMemorySize,
                         SMEM_BYTES);
    dim3 grid(N_DIM / BN, M_DIM / BM);        // (86, 32), nt fastest
    gemm_kernel<<<grid, THREADS, SMEM_BYTES>>>(scale, bias, out);
}

// round 14
// speedup vs baseline: 1.1472x; 1.1472x over previous
#include <cuda_runtime.h>
#include <cuda_fp16.h>
#include <cstdint>
#include <cstddef>

// Problem dims
#define M_DIM 8192
#define K_DIM 4096
#define N_DIM 11008

// GEMM tiling (single-plane fp16 HMMA; 2 CTAs/SM for cross-CTA bubble hiding)
#define BM 128
#define BN 128
#define BKE 64                  // K elements (fp16) per stage = 128 bytes per row
#define STAGES 3
#define NITER (K_DIM / BKE)     // 64
#define THREADS 128             // 4 warps, 2(m) x 2(n) grid, 64x64 warp tile
#define ROWBYTES 128            // XOR-swizzled rows, no padding
#define TILE_A (BM * ROWBYTES)              // 16384
#define TILE_W (BN * ROWBYTES)              // 16384
#define STAGE_BYTES (TILE_A + TILE_W)       // 32768: A | W
#define SMEM_BYTES (STAGES * STAGE_BYTES)   // 98304 -> 2 CTAs/SM

// Scratch (device globals — no runtime allocation allowed)
__device__ __half g_xh[(size_t)M_DIM * K_DIM];   // x as fp16 (11-bit mantissa)
__device__ __half g_w [(size_t)N_DIM * K_DIM];   // Wq as fp16 (exact, |w|<=127)

// ---------------- PTX helpers (portable ISA only: sm_80+) ----------------
__device__ __forceinline__ uint32_t smem_u32(const void* p) {
    uint32_t a;
    asm("{ .reg .u64 t; cvta.to.shared.u64 t, %1; cvt.u32.u64 %0, t; }"
        : "=r"(a) : "l"(p));
    return a;
}
__device__ __forceinline__ void cp16(uint32_t s, const void* g) {
    asm volatile("cp.async.cg.shared.global [%0], [%1], 16;" :: "r"(s), "l"(g) : "memory");
}
#define CP_COMMIT() asm volatile("cp.async.commit_group;" ::: "memory")
#define CP_WAIT(n)  asm volatile("cp.async.wait_group %0;" :: "n"(n) : "memory")

__device__ __forceinline__ void ldsm4(uint32_t* d, uint32_t addr) {
    asm volatile("ldmatrix.sync.aligned.m8n8.x4.shared.b16 {%0,%1,%2,%3}, [%4];"
                 : "=r"(d[0]), "=r"(d[1]), "=r"(d[2]), "=r"(d[3]) : "r"(addr));
}
// C(f32) += A(16x16 f16) * B(16x8 f16)^T
__device__ __forceinline__ void mma_f16(float* c, const uint32_t* a, uint32_t b0, uint32_t b1) {
    asm volatile(
        "mma.sync.aligned.m16n8k16.row.col.f32.f16.f16.f32 "
        "{%0,%1,%2,%3},{%4,%5,%6,%7},{%8,%9},{%0,%1,%2,%3};"
        : "+f"(c[0]), "+f"(c[1]), "+f"(c[2]), "+f"(c[3])
        : "r"(a[0]), "r"(a[1]), "r"(a[2]), "r"(a[3]), "r"(b0), "r"(b1));
}

// ---------------- fused prepass: x -> fp16 AND Wq int32 -> fp16 ----------------
// One kernel so the two DRAM streams overlap (x: 124MB, Wq: 270MB traffic).
__global__ void cvt_fused_kernel(const float4* __restrict__ x, int nx4,
                                 const int4* __restrict__ wq, int nw4) {
    int i = blockIdx.x * blockDim.x + threadIdx.x;
    if (i < nx4) {
        float4 v = x[i];
        __half2 a = __floats2half2_rn(v.x, v.y);
        __half2 b = __floats2half2_rn(v.z, v.w);
        uint2 o = make_uint2(*reinterpret_cast<uint32_t*>(&a), *reinterpret_cast<uint32_t*>(&b));
        reinterpret_cast<uint2*>(g_xh)[i] = o;
    } else {
        int j = i - nx4;
        if (j < nw4) {
            int4 q = wq[j];
            __half2 a = __floats2half2_rn((float)q.x, (float)q.y);
            __half2 b = __floats2half2_rn((float)q.z, (float)q.w);
            uint2 o = make_uint2(*reinterpret_cast<uint32_t*>(&a), *reinterpret_cast<uint32_t*>(&b));
            reinterpret_cast<uint2*>(g_w)[j] = o;
        }
    }
}

// ---------------- GEMM ----------------
// XOR swizzle: row r (128B), 16B chunk c stored at chunk (c ^ (r&7))
__device__ __forceinline__ void load_stage(uint32_t sbase,
                                           const __half* __restrict__ Ax,
                                           const __half* __restrict__ Bw,
                                           int kc, int tid) {
    const int kb = kc * BKE;
    // A: 128 rows x 8 chunks = 1024 chunks; 8 per thread
#pragma unroll
    for (int i = 0; i < 8; ++i) {
        const int q = i * THREADS + tid;
        const int r = q >> 3, c = q & 7;
        const uint32_t so = (uint32_t)r * ROWBYTES + ((c ^ (r & 7)) << 4);
        const size_t ge = (size_t)r * K_DIM + kb + c * 8;
        cp16(sbase + so, Ax + ge);
    }
    // W: 128 rows x 8 chunks = 1024 chunks; 8 per thread
#pragma unroll
    for (int i = 0; i < 8; ++i) {
        const int q = i * THREADS + tid;
        const int r = q >> 3, c = q & 7;
        const uint32_t so = (uint32_t)r * ROWBYTES + ((c ^ (r & 7)) << 4);
        const size_t ge = (size_t)r * K_DIM + kb + c * 8;
        cp16(sbase + TILE_A + so, Bw + ge);
    }
}

__device__ __forceinline__ void tile_compute(uint32_t st, int l, int wm, int wn,
                                             float c[4][8][4]) {
    const uint32_t aB = st;
    const uint32_t bB = st + TILE_A;
    const int r = l & 7, mi = l >> 3;

    // A fragment rows: mat bit0 -> +8 rows, bit1 -> +16B (chunk+1)
    const int arow = ((mi & 1) << 3) + r;
    const int ac0 = (mi >> 1);
    uint32_t aBase[4]; int ax[4];
#pragma unroll
    for (int i = 0; i < 4; ++i) {
        const int rowi = wm + arow + 16 * i;
        aBase[i] = (uint32_t)rowi * ROWBYTES;
        ax[i] = rowi & 7;
    }
    // B fragment rows (W stored [n][k]): mat bit1 -> +8 n-rows, bit0 -> +16B
    const int brow = wn + ((mi >> 1) << 3) + r;
    const int bc0 = (mi & 1);
    uint32_t bBase[4];
#pragma unroll
    for (int nb = 0; nb < 4; ++nb)
        bBase[nb] = (uint32_t)(brow + 16 * nb) * ROWBYTES;
    const int bx = brow & 7;   // invariant under +16

#pragma unroll
    for (int ks = 0; ks < 4; ++ks) {
        const int ca = ac0 + 2 * ks;   // A chunk index for this k-step
        const int cb = bc0 + 2 * ks;   // B chunk index
        uint32_t bt[4][4];
#pragma unroll
        for (int nb = 0; nb < 4; ++nb)
            ldsm4(bt[nb], bB + bBase[nb] + (uint32_t)((cb ^ bx) << 4));  // n 16nb..16nb+15

        uint32_t a[4][4];
#pragma unroll
        for (int i = 0; i < 4; ++i)
            ldsm4(a[i], aB + aBase[i] + (uint32_t)((ca ^ ax[i]) << 4));

#pragma unroll
        for (int i = 0; i < 4; ++i) {
#pragma unroll
            for (int j = 0; j < 8; ++j) {
                mma_f16(c[i][j], a[i], bt[j >> 1][(j & 1) * 2], bt[j >> 1][(j & 1) * 2 + 1]);
            }
        }
    }
}

__global__ void __launch_bounds__(THREADS, 2)
gemm_kernel(const float* __restrict__ scale, const float* __restrict__ bias,
            float* __restrict__ out) {
    extern __shared__ char smem[];
    const uint32_t sb = smem_u32(smem);
    const int tid = threadIdx.x;
    const int wid = tid >> 5;        // 0..3
    const int l = tid & 31;

    const int nt = blockIdx.x;   // fastest -> W (90MB) stays L2-resident across mt sweep
    const int mt = blockIdx.y;
    const size_t mBase = (size_t)mt * BM;
    const size_t nBase = (size_t)nt * BN;

    const __half* Ax = g_xh + mBase * K_DIM;
    const __half* Bw = g_w + nBase * K_DIM;

    const int wm = (wid & 1) * 64;   // 2(m) x 2(n) warp grid, 64x64 warp tile
    const int wn = (wid >> 1) * 64;

    float c[4][8][4];                // 128 f32 accumulators
#pragma unroll
    for (int i = 0; i < 4; ++i)
#pragma unroll
        for (int j = 0; j < 8; ++j)
#pragma unroll
            for (int k = 0; k < 4; ++k) c[i][j][k] = 0.0f;

    // prologue: stages 0..1
#pragma unroll
    for (int s = 0; s < STAGES - 1; ++s) {
        load_stage(sb + s * STAGE_BYTES, Ax, Bw, s, tid);
        CP_COMMIT();
    }

    int sc = 0, sl = STAGES - 1;     // compute-stage and load-stage buffer indices
    for (int it = 0; it < NITER; ++it) {
        CP_WAIT(STAGES - 2);       // stage `it` resident
        __syncthreads();           // all warps done with the buffer being reloaded
        if (it + STAGES - 1 < NITER)
            load_stage(sb + sl * STAGE_BYTES, Ax, Bw, it + STAGES - 1, tid);
        CP_COMMIT();               // empty group in tail keeps counts aligned
        tile_compute(sb + sc * STAGE_BYTES, l, wm, wn, c);
        sc = (sc + 1 == STAGES) ? 0 : sc + 1;
        sl = (sl + 1 == STAGES) ? 0 : sl + 1;
    }

    // ---------------- epilogue: scale + bias + exact GELU ----------------
    const int gid = l >> 2, tig = l & 3;

    float wv[16], bv[16];
#pragma unroll
    for (int j = 0; j < 8; ++j) {
        const size_t n0 = nBase + wn + 8 * j + 2 * tig;
        wv[2 * j] = scale[n0]; wv[2 * j + 1] = scale[n0 + 1];
        bv[2 * j] = bias[n0];  bv[2 * j + 1] = bias[n0 + 1];
    }

#pragma unroll
    for (int i = 0; i < 4; ++i) {
#pragma unroll
        for (int j = 0; j < 8; ++j) {
            const size_t n0 = nBase + wn + 8 * j + 2 * tig;
#pragma unroll
            for (int h = 0; h < 2; ++h) {
                const size_t m = mBase + wm + 16 * i + gid + 8 * h;
                float y0 = fmaf(c[i][j][2 * h],     wv[2 * j],     bv[2 * j]);
                float y1 = fmaf(c[i][j][2 * h + 1], wv[2 * j + 1], bv[2 * j + 1]);
                float g0 = 0.5f * y0 * (1.0f + erff(y0 * 0.70710678118654752f));
                float g1 = 0.5f * y1 * (1.0f + erff(y1 * 0.70710678118654752f));
                float2 vv; vv.x = g0; vv.y = g1;
                __stcg(reinterpret_cast<float2*>(out + m * N_DIM + n0), vv);
            }
        }
    }
}

// ---------------- launch ----------------
extern "C" void kernel_launch(void* const* d_in, const int* in_sizes, int n_in,
                              void* d_out, int out_size) {
    const float* x     = (const float*)d_in[0];
    const int*   Wq    = (const int*)d_in[1];
    const float* scale = (const float*)d_in[2];
    const float* bias  = (const float*)d_in[3];
    float* out = (float*)d_out;
    (void)in_sizes; (void)n_in; (void)out_size;

    // fused prepass: x -> fp16, Wq -> fp16 (overlapped DRAM streams)
    {
        const int nx4 = (M_DIM * K_DIM) / 4;   // 8388608
        const int nw4 = (N_DIM * K_DIM) / 4;   // 11272192
        const int total = nx4 + nw4;
        cvt_fused_kernel<<<(total + 255) / 256, 256>>>((const float4*)x, nx4,
                                                       (const int4*)Wq, nw4);
    }
    // GEMM + fused epilogue (2 CTAs/SM)
    cudaFuncSetAttribute(gemm_kernel, cudaFuncAttributeMaxDynamicSharedMemorySize,
                         SMEM_BYTES);
    dim3 grid(N_DIM / BN, M_DIM / BM);        // (86, 64), nt fastest
    gemm_kernel<<<grid, THREADS, SMEM_BYTES>>>(scale, bias, out);
}